// round 1
// baseline (speedup 1.0000x reference)
#include <cuda_runtime.h>
#include <cstdint>

// Problem constants
#define BB   64
#define CC   20
#define NAA  5
#define HHH  19
#define WWW  19
#define HW   361      // 19*19
#define TT   50
#define NBB  1280     // B*C
#define A4   1805     // NA*H*W
#define CHN  30       // NA*(5+NCPA)
#define EPS12 1e-12f
#define BCEPS 1e-7f
#define THR  0.6f

// Static scratch (no allocations allowed)
__device__ int    g_gt_count[NBB];
__device__ float4 g_gt4[NBB][TT];        // gl, gr, gt, gb (area recomputed)
__device__ int    g_asg_n[NBB];
__device__ int    g_asg_cell[NBB][TT];
__device__ float  g_asg_val[NBB][TT][5]; // tx, ty, tw, th, tconf
__device__ unsigned char g_flag[NBB * A4];
__device__ float  g_tcls[NBB * A4];
__device__ double g_acc[3];              // [0]=coord+conf sum, [1]=cls nll sum, [2]=nsel

__device__ __forceinline__ float sigm(float v) { return 1.0f / (1.0f + expf(-v)); }

// ---------------------------------------------------------------------------
__global__ void k_init() {
    int i = blockIdx.x * blockDim.x + threadIdx.x;
    int n4 = (NBB * A4) / 4;  // 2,310,400 / 4
    uint32_t* f32p = reinterpret_cast<uint32_t*>(g_flag);
    for (int j = i; j < n4; j += gridDim.x * blockDim.x) f32p[j] = 0u;
    if (i < 3) g_acc[i] = 0.0;
}

// ---------------------------------------------------------------------------
// One thread per nb row: serial scan over T targets (overwrite semantics).
__global__ void k_assign(const float* __restrict__ out,
                         const float* __restrict__ target,
                         const float* __restrict__ anchors) {
    int nb = blockIdx.x * blockDim.x + threadIdx.x;
    if (nb >= NBB) return;
    const float* tg = target + (size_t)nb * TT * 5;

    float aw[NAA], ah[NAA];
#pragma unroll
    for (int a = 0; a < NAA; a++) { aw[a] = anchors[2*a]; ah[a] = anchors[2*a+1]; }

    int ng = 0, nasg = 0;
    int cells[TT];

    for (int t = 0; t < TT; t++) {
        float x1 = tg[t*5 + 1];
        if (x1 == 0.0f) break;   // cumprod valid: once 0, all later invalid
        float gx = x1 * (float)WWW;
        float gy = tg[t*5 + 2] * (float)HHH;
        float gw = tg[t*5 + 3] * (float)WWW;
        float gh = tg[t*5 + 4] * (float)HHH;
        float ct = tg[t*5 + 0];

        g_gt4[nb][ng] = make_float4(gx - 0.5f*gw, gx + 0.5f*gw,
                                    gy - 0.5f*gh, gy + 0.5f*gh);
        ng++;

        // best anchor by wh-IoU (first max wins, strict >)
        float best = -1.0f; int bn = 0;
#pragma unroll
        for (int a = 0; a < NAA; a++) {
            float inter = fminf(gw, aw[a]) * fminf(gh, ah[a]);
            float un = gw*gh + aw[a]*ah[a] - inter;
            float r = inter / fmaxf(un, EPS12);
            if (r > best) { best = r; bn = a; }
        }
        int gi = (int)gx;
        int gj = (int)gy;

        // prediction at (nb, bn, gj, gi)
        const float* ob = out + ((size_t)nb * CHN + bn*6) * HW + gj*WWW + gi;
        float px = sigm(ob[0])       + (float)gi;
        float py = sigm(ob[HW])      + (float)gj;
        float pw = expf(ob[2*HW]) * aw[bn];
        float ph = expf(ob[3*HW]) * ah[bn];

        float l  = fmaxf(gx - 0.5f*gw, px - 0.5f*pw);
        float r2 = fminf(gx + 0.5f*gw, px + 0.5f*pw);
        float tp = fmaxf(gy - 0.5f*gh, py - 0.5f*ph);
        float bt = fminf(gy + 0.5f*gh, py + 0.5f*ph);
        float inter = fmaxf(r2 - l, 0.0f) * fmaxf(bt - tp, 0.0f);
        float un = gw*gh + pw*ph - inter;
        float iou = inter / fmaxf(un, EPS12);

        int cell = bn * HW + gj * WWW + gi;
        int slot = -1;
        for (int k = 0; k < nasg; k++) if (cells[k] == cell) slot = k;
        if (slot < 0) { slot = nasg++; cells[slot] = cell; g_asg_cell[nb][slot] = cell; }
        g_asg_val[nb][slot][0] = gx - (float)gi;
        g_asg_val[nb][slot][1] = gy - (float)gj;
        g_asg_val[nb][slot][2] = logf(fmaxf(gw, EPS12) / aw[bn]);
        g_asg_val[nb][slot][3] = logf(fmaxf(gh, EPS12) / ah[bn]);
        g_asg_val[nb][slot][4] = iou;

        size_t di = (size_t)nb * A4 + cell;
        g_flag[di] = 1;
        g_tcls[di] = ct;
    }
    g_gt_count[nb] = ng;
    g_asg_n[nb]    = nasg;
}

// ---------------------------------------------------------------------------
// Fused dense losses: x/y BCE + w/h MSE + conf MSE. Grid: (ceil(A4/256), NB).
__global__ void k_main(const float* __restrict__ out,
                       const float* __restrict__ anchors) {
    int nb = blockIdx.y;
    int tid = threadIdx.x;

    __shared__ int s_ng, s_nasg;
    __shared__ float4 s_gt4[TT];
    __shared__ int    s_cell[TT];
    __shared__ float  s_val[TT][5];

    if (tid == 0) { s_ng = g_gt_count[nb]; s_nasg = g_asg_n[nb]; }
    for (int i = tid; i < TT; i += blockDim.x) {
        s_gt4[i]  = g_gt4[nb][i];
        s_cell[i] = g_asg_cell[nb][i];
    }
    for (int i = tid; i < TT*5; i += blockDim.x)
        (&s_val[0][0])[i] = (&g_asg_val[nb][0][0])[i];
    __syncthreads();

    double contrib = 0.0;
    int idx = blockIdx.x * blockDim.x + tid;
    if (idx < A4) {
        int na = idx / HW;
        int hw = idx - na * HW;
        int hh = hw / WWW;
        int ww = hw - hh * WWW;

        const float* ob = out + ((size_t)nb * CHN + na*6) * HW + hw;
        float o0 = ob[0], o1 = ob[HW], o2 = ob[2*HW], o3 = ob[3*HW], o4 = ob[4*HW];

        float x = sigm(o0), y = sigm(o1), conf = sigm(o4);
        float aw = anchors[2*na], ah = anchors[2*na + 1];
        float px = x + (float)ww;
        float py = y + (float)hh;
        float pw = expf(o2) * aw;
        float ph = expf(o3) * ah;
        float pl = px - 0.5f*pw, pr = px + 0.5f*pw;
        float pt = py - 0.5f*ph, pb = py + 0.5f*ph;
        float pa = pw * ph;

        // conf_mask0: any valid gt with IoU > THR?  (division-free)
        bool over = false;
        int ng = s_ng;
        for (int t = 0; t < ng; t++) {
            float4 g = s_gt4[t];
            float iw = fminf(pr, g.y) - fmaxf(pl, g.x);
            float ih = fminf(pb, g.w) - fmaxf(pt, g.z);
            float inter = fmaxf(iw, 0.0f) * fmaxf(ih, 0.0f);
            float ga = (g.y - g.x) * (g.w - g.z);
            float un = pa + ga - inter;
            over = over || (inter > THR * fmaxf(un, EPS12));
        }
        float cfm = over ? 0.0f : 1.0f;
        float tx = 0.5f, ty = 0.5f, tw = 0.0f, th = 0.0f, tconf = 0.0f;
        int nasg = s_nasg;
        for (int k = 0; k < nasg; k++) {
            if (s_cell[k] == idx) {
                cfm = 1.0f;
                tx = s_val[k][0]; ty = s_val[k][1];
                tw = s_val[k][2]; th = s_val[k][3];
                tconf = s_val[k][4];
            }
        }

        float pxc = fminf(fmaxf(x, BCEPS), 1.0f - BCEPS);
        float pyc = fminf(fmaxf(y, BCEPS), 1.0f - BCEPS);
        float bx = -(tx * logf(pxc) + (1.0f - tx) * logf(1.0f - pxc));
        float by = -(ty * logf(pyc) + (1.0f - ty) * logf(1.0f - pyc));
        float dw = o2 - tw, dh = o3 - th;
        float dc = cfm * (conf - tconf);
        contrib = (double)(bx + by + 0.5f * (dw*dw + dh*dh) + 0.5f * dc*dc);
    }

    // block reduce (256 threads = 8 warps)
#pragma unroll
    for (int o = 16; o > 0; o >>= 1)
        contrib += __shfl_down_sync(0xffffffffu, contrib, o);
    __shared__ double s_red[8];
    if ((tid & 31) == 0) s_red[tid >> 5] = contrib;
    __syncthreads();
    if (tid == 0) {
        double s = 0.0;
#pragma unroll
        for (int wgi = 0; wgi < 8; wgi++) s += s_red[wgi];
        atomicAdd(&g_acc[0], s);
    }
}

// ---------------------------------------------------------------------------
// Class loss: per (b, a4) cell, sel iff exactly one of C rows assigned here.
__global__ void k_cls(const float* __restrict__ out) {
    int idx = blockIdx.x * blockDim.x + threadIdx.x;
    int tid = threadIdx.x;
    double nll = 0.0, ns = 0.0;
    if (idx < BB * A4) {
        int b  = idx / A4;
        int a4 = idx - b * A4;
        int na = a4 / HW;
        int hw = a4 - na * HW;

        size_t fbase = (size_t)b * CC * A4 + a4;
        int cnt = 0; float tsum = 0.0f;
#pragma unroll
        for (int c = 0; c < CC; c++) {
            if (g_flag[fbase + (size_t)c * A4]) { cnt++; tsum += g_tcls[fbase + (size_t)c * A4]; }
        }
        if (cnt == 1) {
            int label = (int)tsum;
            size_t obase = ((size_t)b * CC * CHN + na*6 + 5) * HW + hw;
            // online logsumexp, single pass
            float m = -1e30f, s = 0.0f, llab = 0.0f;
#pragma unroll
            for (int c = 0; c < CC; c++) {
                float l = out[obase + (size_t)c * CHN * HW];
                if (c == label) llab = l;
                if (l > m) { s = s * expf(m - l) + 1.0f; m = l; }
                else       { s += expf(l - m); }
            }
            float lse = m + logf(s);
            nll = (double)(lse - llab);
            ns  = 1.0;
        }
    }
#pragma unroll
    for (int o = 16; o > 0; o >>= 1) {
        nll += __shfl_down_sync(0xffffffffu, nll, o);
        ns  += __shfl_down_sync(0xffffffffu, ns,  o);
    }
    __shared__ double s_n[8], s_c[8];
    if ((tid & 31) == 0) { s_n[tid >> 5] = nll; s_c[tid >> 5] = ns; }
    __syncthreads();
    if (tid == 0) {
        double a = 0.0, bsum = 0.0;
#pragma unroll
        for (int w = 0; w < 8; w++) { a += s_n[w]; bsum += s_c[w]; }
        atomicAdd(&g_acc[1], a);
        atomicAdd(&g_acc[2], bsum);
    }
}

// ---------------------------------------------------------------------------
__global__ void k_final(float* __restrict__ res) {
    double N = (double)NBB * (double)A4;
    res[0] = (float)(g_acc[0] / N + g_acc[1] / fmax(g_acc[2], 1.0));
}

// ---------------------------------------------------------------------------
extern "C" void kernel_launch(void* const* d_in, const int* in_sizes, int n_in,
                              void* d_out, int out_size) {
    const float* out_t   = (const float*)d_in[0];
    const float* target  = (const float*)d_in[1];
    const float* anchors = (const float*)d_in[2];
    float* res = (float*)d_out;

    k_init<<<256, 256>>>();
    k_assign<<<(NBB + 127) / 128, 128>>>(out_t, target, anchors);
    dim3 gmain((A4 + 255) / 256, NBB);
    k_main<<<gmain, 256>>>(out_t, anchors);
    k_cls<<<(BB * A4 + 255) / 256, 256>>>(out_t);
    k_final<<<1, 1>>>(res);
}

// round 2
// speedup vs baseline: 2.1691x; 2.1691x over previous
#include <cuda_runtime.h>
#include <cstdint>

// Problem constants
#define BB     64
#define CC     20
#define NAA    5
#define HHH    19
#define WWW    19
#define HW     361      // 19*19
#define TT     50
#define NBB    1280     // B*C
#define A4     1805     // NA*H*W
#define CHN    30       // NA*(5+NCPA)
#define EPS12  1e-12f
#define BCEPS  1e-7f
#define THR    0.6f
#define FLAGSTR 1808    // A4 padded to /4 for word zeroing
#define MAIN_BLOCKS (NBB * 8)   // 8 chunks of 256 cover A4=1805
#define CLS_BLOCKS  452         // ceil(64*1805/256)

// Static scratch (no allocations allowed)
__device__ int    g_gt_count[NBB];
__device__ float4 g_gt4[NBB][TT];        // gl, gr, gt, gb
__device__ float  g_gtc[NBB][TT];        // 0.375 * gt_area
__device__ int    g_asg_n[NBB];
__device__ int    g_asg_cell[NBB][TT];
__device__ float  g_asg_val[NBB][TT][5]; // tx, ty, tw, th, tconf
__device__ unsigned char g_flag[NBB * FLAGSTR];
__device__ float  g_tcls[NBB * FLAGSTR];
__device__ double g_acc[3];              // [0]=dense sum, [1]=cls nll, [2]=nsel

__device__ __forceinline__ float fsigm(float v) {
    return __fdividef(1.0f, 1.0f + __expf(-v));
}

// ---------------------------------------------------------------------------
// One block (64 threads) per nb row. Zeroes its flag row, loads targets to
// shared, resolves last-writer-wins assignment in parallel.
__global__ void k_assign(const float* __restrict__ out,
                         const float* __restrict__ target,
                         const float* __restrict__ anchors) {
    int nb = blockIdx.x;
    int t  = threadIdx.x;

    // zero this row's flags (word writes) + global accumulators
    uint32_t* frow = reinterpret_cast<uint32_t*>(g_flag + (size_t)nb * FLAGSTR);
    for (int i = t; i < FLAGSTR / 4; i += 64) frow[i] = 0u;
    if (nb == 0 && t < 3) g_acc[t] = 0.0;

    __shared__ float s_tg[TT * 5];
    __shared__ int   s_ng;
    __shared__ int   s_nasg;
    __shared__ int   s_cell[TT];

    const float* tg = target + (size_t)nb * TT * 5;
    for (int i = t; i < TT * 5; i += 64) s_tg[i] = tg[i];
    __syncthreads();

    if (t == 0) {
        int ng = 0;
        while (ng < TT && s_tg[ng * 5 + 1] != 0.0f) ng++;
        s_ng = ng;
        s_nasg = 0;
    }
    __syncthreads();
    int ng = s_ng;

    float gx = 0.f, gy = 0.f, gw = 0.f, gh = 0.f, ct = 0.f;
    int gi = 0, gj = 0, bn = 0, cell = -1;
    float awb = 1.f, ahb = 1.f;

    if (t < ng) {
        ct = s_tg[t * 5 + 0];
        gx = s_tg[t * 5 + 1] * (float)WWW;
        gy = s_tg[t * 5 + 2] * (float)HHH;
        gw = s_tg[t * 5 + 3] * (float)WWW;
        gh = s_tg[t * 5 + 4] * (float)HHH;

        float best = -1.0f;
#pragma unroll
        for (int a = 0; a < NAA; a++) {
            float aw = __ldg(&anchors[2 * a]);
            float ah = __ldg(&anchors[2 * a + 1]);
            float inter = fminf(gw, aw) * fminf(gh, ah);
            float un = gw * gh + aw * ah - inter;
            float r = __fdividef(inter, fmaxf(un, EPS12));
            if (r > best) { best = r; bn = a; awb = aw; ahb = ah; }
        }
        gi = (int)gx;
        gj = (int)gy;
        cell = bn * HW + gj * WWW + gi;
        s_cell[t] = cell;

        g_gt4[nb][t] = make_float4(gx - 0.5f * gw, gx + 0.5f * gw,
                                   gy - 0.5f * gh, gy + 0.5f * gh);
        g_gtc[nb][t] = 0.375f * gw * gh;
        g_flag[(size_t)nb * FLAGSTR + cell] = 1;
    }
    __syncthreads();

    if (t < ng) {
        // last writer wins for this cell
        bool win = true;
        for (int t2 = t + 1; t2 < ng; t2++)
            if (s_cell[t2] == cell) win = false;

        // every valid target writes tcls? ref overwrites; only winner's value
        // survives -> winner writes it.
        if (win) {
            g_tcls[(size_t)nb * FLAGSTR + cell] = ct;

            const float* ob = out + ((size_t)nb * CHN + bn * 6) * HW + gj * WWW + gi;
            float px = fsigm(ob[0])    + (float)gi;
            float py = fsigm(ob[HW])   + (float)gj;
            float pw = __expf(ob[2 * HW]) * awb;
            float ph = __expf(ob[3 * HW]) * ahb;

            float l  = fmaxf(gx - 0.5f * gw, px - 0.5f * pw);
            float r2 = fminf(gx + 0.5f * gw, px + 0.5f * pw);
            float tp = fmaxf(gy - 0.5f * gh, py - 0.5f * ph);
            float bt = fminf(gy + 0.5f * gh, py + 0.5f * ph);
            float inter = fmaxf(r2 - l, 0.0f) * fmaxf(bt - tp, 0.0f);
            float un = gw * gh + pw * ph - inter;
            float iou = __fdividef(inter, fmaxf(un, EPS12));

            int slot = atomicAdd(&s_nasg, 1);
            g_asg_cell[nb][slot] = cell;
            g_asg_val[nb][slot][0] = gx - (float)gi;
            g_asg_val[nb][slot][1] = gy - (float)gj;
            g_asg_val[nb][slot][2] = __logf(__fdividef(fmaxf(gw, EPS12), awb));
            g_asg_val[nb][slot][3] = __logf(__fdividef(fmaxf(gh, EPS12), ahb));
            g_asg_val[nb][slot][4] = iou;
        }
    }
    __syncthreads();
    if (t == 0) {
        g_gt_count[nb] = ng;
        g_asg_n[nb]    = s_nasg;
    }
}

// ---------------------------------------------------------------------------
// Fused dense losses + class loss in ONE launch. Blocks [0, MAIN_BLOCKS) do
// the per-cell coord/conf losses; blocks beyond do the class NLL.
__global__ void k_fused(const float* __restrict__ out,
                        const float* __restrict__ anchors) {
    int tid = threadIdx.x;

    if (blockIdx.x < MAIN_BLOCKS) {
        int nb    = blockIdx.x >> 3;
        int chunk = blockIdx.x & 7;
        int idx   = chunk * 256 + tid;

        // issue global loads early
        float o0 = 0.f, o1 = 0.f, o2 = 0.f, o3 = 0.f, o4 = 0.f;
        int na = 0, hw = 0, hh = 0, ww = 0;
        bool live = idx < A4;
        if (live) {
            na = idx / HW;
            hw = idx - na * HW;
            hh = hw / WWW;
            ww = hw - hh * WWW;
            const float* ob = out + ((size_t)nb * CHN + na * 6) * HW + hw;
            o0 = ob[0]; o1 = ob[HW]; o2 = ob[2 * HW]; o3 = ob[3 * HW]; o4 = ob[4 * HW];
        }

        __shared__ int    s_ng, s_nasg;
        __shared__ float4 s_gt4[TT];
        __shared__ float  s_gc[TT];
        __shared__ int    s_cell[TT];
        __shared__ float  s_val[TT][5];
        __shared__ uint32_t s_bits[57];

        if (tid == 0) { s_ng = g_gt_count[nb]; s_nasg = g_asg_n[nb]; }
        if (tid < 57) s_bits[tid] = 0u;
        __syncthreads();
        int ng = s_ng, nasg = s_nasg;
        for (int i = tid; i < ng; i += 256) {
            s_gt4[i] = g_gt4[nb][i];
            s_gc[i]  = g_gtc[nb][i];
        }
        for (int i = tid; i < nasg; i += 256) {
            int c = g_asg_cell[nb][i];
            s_cell[i] = c;
            atomicOr(&s_bits[c >> 5], 1u << (c & 31));
        }
        for (int i = tid; i < nasg * 5; i += 256)
            (&s_val[0][0])[i] = (&g_asg_val[nb][0][0])[i];
        __syncthreads();

        double contrib = 0.0;
        if (live) {
            float x = fsigm(o0), y = fsigm(o1), conf = fsigm(o4);
            float aw = __ldg(&anchors[2 * na]), ah = __ldg(&anchors[2 * na + 1]);
            float px = x + (float)ww;
            float py = y + (float)hh;
            float pw = __expf(o2) * aw;
            float ph = __expf(o3) * ah;
            float pl = px - 0.5f * pw, pr = px + 0.5f * pw;
            float pt = py - 0.5f * ph, pb = py + 0.5f * ph;
            float k1 = 0.375f * pw * ph;   // 0.375 * pa

            // IoU > 0.6  <=>  inter > 0.375*(pa+ga); union >= max(pa,ga) >> eps
            bool over = false;
            for (int t = 0; t < ng; t++) {
                float4 g = s_gt4[t];
                float iw = fminf(pr, g.y) - fmaxf(pl, g.x);
                float ih = fminf(pb, g.w) - fmaxf(pt, g.z);
                float inter = fmaxf(iw, 0.0f) * fmaxf(ih, 0.0f);
                over = over || (inter > k1 + s_gc[t]);
            }
            float cfm = over ? 0.0f : 1.0f;
            float tx = 0.5f, ty = 0.5f, tw = 0.0f, th = 0.0f, tconf = 0.0f;
            if (s_bits[idx >> 5] & (1u << (idx & 31))) {
                for (int k = 0; k < nasg; k++) {
                    if (s_cell[k] == idx) {
                        cfm = 1.0f;
                        tx = s_val[k][0]; ty = s_val[k][1];
                        tw = s_val[k][2]; th = s_val[k][3];
                        tconf = s_val[k][4];
                    }
                }
            }

            float pxc = fminf(fmaxf(x, BCEPS), 1.0f - BCEPS);
            float pyc = fminf(fmaxf(y, BCEPS), 1.0f - BCEPS);
            float bx = -(tx * __logf(pxc) + (1.0f - tx) * __logf(1.0f - pxc));
            float by = -(ty * __logf(pyc) + (1.0f - ty) * __logf(1.0f - pyc));
            float dw = o2 - tw, dh = o3 - th;
            float dc = cfm * (conf - tconf);
            contrib = (double)(bx + by + 0.5f * (dw * dw + dh * dh) + 0.5f * dc * dc);
        }

#pragma unroll
        for (int o = 16; o > 0; o >>= 1)
            contrib += __shfl_down_sync(0xffffffffu, contrib, o);
        __shared__ double s_red[8];
        if ((tid & 31) == 0) s_red[tid >> 5] = contrib;
        __syncthreads();
        if (tid == 0) {
            double s = 0.0;
#pragma unroll
            for (int w = 0; w < 8; w++) s += s_red[w];
            atomicAdd(&g_acc[0], s);
        }
    } else {
        // ---- class-loss blocks ----
        int idx = (blockIdx.x - MAIN_BLOCKS) * 256 + tid;
        double nll = 0.0, ns = 0.0;
        if (idx < BB * A4) {
            int b  = idx / A4;
            int a4 = idx - b * A4;
            int na = a4 / HW;
            int hw = a4 - na * HW;

            size_t fbase = (size_t)b * CC * FLAGSTR + a4;
            int cnt = 0; float tsum = 0.0f;
#pragma unroll
            for (int c = 0; c < CC; c++) {
                if (g_flag[fbase + (size_t)c * FLAGSTR]) {
                    cnt++;
                    tsum += g_tcls[fbase + (size_t)c * FLAGSTR];
                }
            }
            if (cnt == 1) {
                int label = (int)tsum;
                size_t obase = ((size_t)b * CC * CHN + na * 6 + 5) * HW + hw;
                float m = -1e30f, s = 0.0f, llab = 0.0f;
#pragma unroll
                for (int c = 0; c < CC; c++) {
                    float l = out[obase + (size_t)c * CHN * HW];
                    if (c == label) llab = l;
                    if (l > m) { s = s * __expf(m - l) + 1.0f; m = l; }
                    else       { s += __expf(l - m); }
                }
                float lse = m + __logf(s);
                nll = (double)(lse - llab);
                ns  = 1.0;
            }
        }
#pragma unroll
        for (int o = 16; o > 0; o >>= 1) {
            nll += __shfl_down_sync(0xffffffffu, nll, o);
            ns  += __shfl_down_sync(0xffffffffu, ns,  o);
        }
        __shared__ double s_n[8], s_c[8];
        if ((tid & 31) == 0) { s_n[tid >> 5] = nll; s_c[tid >> 5] = ns; }
        __syncthreads();
        if (tid == 0) {
            double a = 0.0, bsum = 0.0;
#pragma unroll
            for (int w = 0; w < 8; w++) { a += s_n[w]; bsum += s_c[w]; }
            atomicAdd(&g_acc[1], a);
            atomicAdd(&g_acc[2], bsum);
        }
    }
}

// ---------------------------------------------------------------------------
__global__ void k_final(float* __restrict__ res) {
    double N = (double)NBB * (double)A4;
    res[0] = (float)(g_acc[0] / N + g_acc[1] / fmax(g_acc[2], 1.0));
}

// ---------------------------------------------------------------------------
extern "C" void kernel_launch(void* const* d_in, const int* in_sizes, int n_in,
                              void* d_out, int out_size) {
    const float* out_t   = (const float*)d_in[0];
    const float* target  = (const float*)d_in[1];
    const float* anchors = (const float*)d_in[2];
    float* res = (float*)d_out;

    k_assign<<<NBB, 64>>>(out_t, target, anchors);
    k_fused<<<MAIN_BLOCKS + CLS_BLOCKS, 256>>>(out_t, anchors);
    k_final<<<1, 1>>>(res);
}

// round 3
// speedup vs baseline: 2.4922x; 1.1490x over previous
#include <cuda_runtime.h>
#include <cstdint>

// Problem constants
#define BB     64
#define CC     20
#define NAA    5
#define HHH    19
#define WWW    19
#define HW     361      // 19*19
#define TT     50
#define NBB    1280     // B*C
#define A4     1805     // NA*H*W
#define CHN    30       // NA*(5+NCPA)
#define EPS12  1e-12f
#define BCEPS  1e-7f
#define MAIN_BLOCKS (NBB * 4)                 // 4 chunks of 512 cells (2/thread)
#define CLS_N   (BB * A4)                     // 115520
#define CLS_BLOCKS ((CLS_N + 255) / 256)      // 452

// Static scratch (no allocations allowed)
__device__ int    g_gt_count[NBB];
__device__ float4 g_gt4[NBB][TT];        // gl, gr, gt, gb (padded with dummies)
__device__ float  g_gtc[NBB][TT];        // 0.375*area (1e30 for pad)
__device__ int    g_asg_n[NBB];
__device__ int    g_asg_cell[NBB][TT];
__device__ float  g_asg_val[NBB][TT][5]; // tx, ty, tw, th, tconf
__device__ int    g_cnt[CLS_N];          // assignments per (b, a4) across C
__device__ float  g_tsum[CLS_N];         // sum of winner class ids
__device__ double g_acc[3];              // [0]=dense, [1]=cls nll, [2]=nsel

__device__ __forceinline__ float fsigm(float v) {
    return __fdividef(1.0f, 1.0f + __expf(-v));
}

// ---------------------------------------------------------------------------
__global__ void k_zero() {
    int i = blockIdx.x * blockDim.x + threadIdx.x;
    if (i < CLS_N) { g_cnt[i] = 0; g_tsum[i] = 0.0f; }
    if (i < 3) g_acc[i] = 0.0;
}

// ---------------------------------------------------------------------------
// One block (64 threads) per nb row.
__global__ void k_assign(const float* __restrict__ out,
                         const float* __restrict__ target,
                         const float* __restrict__ anchors) {
    int nb = blockIdx.x;
    int t  = threadIdx.x;

    __shared__ float s_tg[TT * 5];
    __shared__ int   s_ng, s_nasg;
    __shared__ int   s_cell[TT];

    const float* tg = target + (size_t)nb * TT * 5;
    for (int i = t; i < TT * 5; i += 64) s_tg[i] = tg[i];
    __syncthreads();

    if (t == 0) {
        int ng = 0;
        while (ng < TT && s_tg[ng * 5 + 1] != 0.0f) ng++;
        s_ng = ng;
        s_nasg = 0;
    }
    __syncthreads();
    int ng = s_ng;

    float gx = 0.f, gy = 0.f, gw = 0.f, gh = 0.f, ct = 0.f;
    int gi = 0, gj = 0, bn = 0, cell = -1;
    float awb = 1.f, ahb = 1.f;

    if (t < ng) {
        ct = s_tg[t * 5 + 0];
        gx = s_tg[t * 5 + 1] * (float)WWW;
        gy = s_tg[t * 5 + 2] * (float)HHH;
        gw = s_tg[t * 5 + 3] * (float)WWW;
        gh = s_tg[t * 5 + 4] * (float)HHH;

        float best = -1.0f;
#pragma unroll
        for (int a = 0; a < NAA; a++) {
            float aw = __ldg(&anchors[2 * a]);
            float ah = __ldg(&anchors[2 * a + 1]);
            float inter = fminf(gw, aw) * fminf(gh, ah);
            float un = gw * gh + aw * ah - inter;
            float r = __fdividef(inter, fmaxf(un, EPS12));
            if (r > best) { best = r; bn = a; awb = aw; ahb = ah; }
        }
        gi = (int)gx;
        gj = (int)gy;
        cell = bn * HW + gj * WWW + gi;
        s_cell[t] = cell;

        g_gt4[nb][t] = make_float4(gx - 0.5f * gw, gx + 0.5f * gw,
                                   gy - 0.5f * gh, gy + 0.5f * gh);
        g_gtc[nb][t] = 0.375f * gw * gh;
    } else if (t < TT) {
        // dummy pad entry: never triggers the IoU threshold test
        g_gt4[nb][t] = make_float4(0.f, 0.f, 0.f, 0.f);
        g_gtc[nb][t] = 1e30f;
    }
    __syncthreads();

    if (t < ng) {
        // last writer wins for this cell within this nb row
        bool win = true;
        for (int t2 = t + 1; t2 < ng; t2++)
            if (s_cell[t2] == cell) win = false;

        if (win) {
            int b = nb / CC;
            atomicAdd(&g_cnt[b * A4 + cell], 1);
            atomicAdd(&g_tsum[b * A4 + cell], ct);

            const float* ob = out + ((size_t)nb * CHN + bn * 6) * HW + gj * WWW + gi;
            float px = fsigm(ob[0])    + (float)gi;
            float py = fsigm(ob[HW])   + (float)gj;
            float pw = __expf(ob[2 * HW]) * awb;
            float ph = __expf(ob[3 * HW]) * ahb;

            float l  = fmaxf(gx - 0.5f * gw, px - 0.5f * pw);
            float r2 = fminf(gx + 0.5f * gw, px + 0.5f * pw);
            float tp = fmaxf(gy - 0.5f * gh, py - 0.5f * ph);
            float bt = fminf(gy + 0.5f * gh, py + 0.5f * ph);
            float inter = fmaxf(r2 - l, 0.0f) * fmaxf(bt - tp, 0.0f);
            float un = gw * gh + pw * ph - inter;
            float iou = __fdividef(inter, fmaxf(un, EPS12));

            int slot = atomicAdd(&s_nasg, 1);
            g_asg_cell[nb][slot] = cell;
            g_asg_val[nb][slot][0] = gx - (float)gi;
            g_asg_val[nb][slot][1] = gy - (float)gj;
            g_asg_val[nb][slot][2] = __logf(__fdividef(fmaxf(gw, EPS12), awb));
            g_asg_val[nb][slot][3] = __logf(__fdividef(fmaxf(gh, EPS12), ahb));
            g_asg_val[nb][slot][4] = iou;
        }
    }
    __syncthreads();
    if (t == 0) {
        g_gt_count[nb] = ng;
        g_asg_n[nb]    = s_nasg;
    }
}

// ---------------------------------------------------------------------------
// Fused dense losses (2 cells/thread) + class loss in ONE launch.
__global__ void k_fused(const float* __restrict__ out,
                        const float* __restrict__ anchors) {
    int tid = threadIdx.x;

    if (blockIdx.x < MAIN_BLOCKS) {
        int nb    = blockIdx.x >> 2;
        int chunk = blockIdx.x & 3;
        int idx0  = chunk * 512 + tid;
        int idx1  = idx0 + 256;

        __shared__ int    s_ng, s_nasg;
        __shared__ float4 s_gt4[TT];
        __shared__ float  s_gc[TT];
        __shared__ int    s_cell[TT];
        __shared__ float  s_val[TT][5];
        __shared__ uint32_t s_bits[57];

        if (tid == 0) { s_ng = g_gt_count[nb]; s_nasg = g_asg_n[nb]; }
        if (tid < 57) s_bits[tid] = 0u;
        __syncthreads();
        int ng = s_ng, nasg = s_nasg;
        int ngp = ((ng + 4) / 5) * 5;   // padded entries are valid dummies
        for (int i = tid; i < ngp; i += 256) {
            s_gt4[i] = g_gt4[nb][i];
            s_gc[i]  = g_gtc[nb][i];
        }
        for (int i = tid; i < nasg; i += 256) {
            int c = g_asg_cell[nb][i];
            s_cell[i] = c;
            atomicOr(&s_bits[c >> 5], 1u << (c & 31));
        }
        for (int i = tid; i < nasg * 5; i += 256)
            (&s_val[0][0])[i] = (&g_asg_val[nb][0][0])[i];

        // cell setup (global loads issued before the sync to overlap)
        bool lv0 = idx0 < A4, lv1 = idx1 < A4;
        float a0o[5], a1o[5];
        int na0 = 0, hw0 = 0, na1 = 0, hw1 = 0;
        if (lv0) {
            na0 = idx0 / HW; hw0 = idx0 - na0 * HW;
            const float* ob = out + ((size_t)nb * CHN + na0 * 6) * HW + hw0;
#pragma unroll
            for (int j = 0; j < 5; j++) a0o[j] = ob[j * HW];
        }
        if (lv1) {
            na1 = idx1 / HW; hw1 = idx1 - na1 * HW;
            const float* ob = out + ((size_t)nb * CHN + na1 * 6) * HW + hw1;
#pragma unroll
            for (int j = 0; j < 5; j++) a1o[j] = ob[j * HW];
        }
        __syncthreads();

        float pl0 = 0.f, pr0 = -1.f, pt0 = 0.f, pb0 = -1.f, k10 = 1e30f;
        float pl1 = 0.f, pr1 = -1.f, pt1 = 0.f, pb1 = -1.f, k11 = 1e30f;
        float x0 = 0.f, y0 = 0.f, c0 = 0.f, x1v = 0.f, y1v = 0.f, c1v = 0.f;
        if (lv0) {
            int hh = hw0 / WWW, ww = hw0 - hh * WWW;
            x0 = fsigm(a0o[0]); y0 = fsigm(a0o[1]); c0 = fsigm(a0o[4]);
            float aw = __ldg(&anchors[2 * na0]), ah = __ldg(&anchors[2 * na0 + 1]);
            float px = x0 + (float)ww, py = y0 + (float)hh;
            float pw = __expf(a0o[2]) * aw, ph = __expf(a0o[3]) * ah;
            pl0 = px - 0.5f * pw; pr0 = px + 0.5f * pw;
            pt0 = py - 0.5f * ph; pb0 = py + 0.5f * ph;
            k10 = 0.375f * pw * ph;
        }
        if (lv1) {
            int hh = hw1 / WWW, ww = hw1 - hh * WWW;
            x1v = fsigm(a1o[0]); y1v = fsigm(a1o[1]); c1v = fsigm(a1o[4]);
            float aw = __ldg(&anchors[2 * na1]), ah = __ldg(&anchors[2 * na1 + 1]);
            float px = x1v + (float)ww, py = y1v + (float)hh;
            float pw = __expf(a1o[2]) * aw, ph = __expf(a1o[3]) * ah;
            pl1 = px - 0.5f * pw; pr1 = px + 0.5f * pw;
            pt1 = py - 0.5f * ph; pb1 = py + 0.5f * ph;
            k11 = 0.375f * pw * ph;
        }

        // IoU>0.6 over gts, division-free; dummies (gc=1e30) never pass
        bool ov0 = false, ov1 = false;
#pragma unroll 5
        for (int t = 0; t < ngp; t++) {
            float4 g = s_gt4[t];
            float gcv = s_gc[t];
            float iw0 = fminf(pr0, g.y) - fmaxf(pl0, g.x);
            float ih0 = fminf(pb0, g.w) - fmaxf(pt0, g.z);
            float in0 = fmaxf(iw0, 0.0f) * fmaxf(ih0, 0.0f);
            ov0 = ov0 || (in0 > k10 + gcv);
            float iw1 = fminf(pr1, g.y) - fmaxf(pl1, g.x);
            float ih1 = fminf(pb1, g.w) - fmaxf(pt1, g.z);
            float in1 = fmaxf(iw1, 0.0f) * fmaxf(ih1, 0.0f);
            ov1 = ov1 || (in1 > k11 + gcv);
        }

        double contrib = 0.0;
#pragma unroll
        for (int cell2 = 0; cell2 < 2; cell2++) {
            bool live = cell2 ? lv1 : lv0;
            if (!live) continue;
            int idx = cell2 ? idx1 : idx0;
            float x = cell2 ? x1v : x0, y = cell2 ? y1v : y0, conf = cell2 ? c1v : c0;
            float o2 = cell2 ? a1o[2] : a0o[2], o3 = cell2 ? a1o[3] : a0o[3];
            bool over = cell2 ? ov1 : ov0;

            float cfm = over ? 0.0f : 1.0f;
            float tx = 0.5f, ty = 0.5f, tw = 0.0f, th = 0.0f, tconf = 0.0f;
            if (s_bits[idx >> 5] & (1u << (idx & 31))) {
                for (int k = 0; k < nasg; k++) {
                    if (s_cell[k] == idx) {
                        cfm = 1.0f;
                        tx = s_val[k][0]; ty = s_val[k][1];
                        tw = s_val[k][2]; th = s_val[k][3];
                        tconf = s_val[k][4];
                    }
                }
            }
            float pxc = fminf(fmaxf(x, BCEPS), 1.0f - BCEPS);
            float pyc = fminf(fmaxf(y, BCEPS), 1.0f - BCEPS);
            float bx = -(tx * __logf(pxc) + (1.0f - tx) * __logf(1.0f - pxc));
            float by = -(ty * __logf(pyc) + (1.0f - ty) * __logf(1.0f - pyc));
            float dw = o2 - tw, dh = o3 - th;
            float dc = cfm * (conf - tconf);
            contrib += (double)(bx + by + 0.5f * (dw * dw + dh * dh) + 0.5f * dc * dc);
        }

#pragma unroll
        for (int o = 16; o > 0; o >>= 1)
            contrib += __shfl_down_sync(0xffffffffu, contrib, o);
        __shared__ double s_red[8];
        if ((tid & 31) == 0) s_red[tid >> 5] = contrib;
        __syncthreads();
        if (tid == 0) {
            double s = 0.0;
#pragma unroll
            for (int w = 0; w < 8; w++) s += s_red[w];
            atomicAdd(&g_acc[0], s);
        }
    } else {
        // ---- class-loss blocks ----
        int idx = (blockIdx.x - MAIN_BLOCKS) * 256 + tid;
        double nll = 0.0, ns = 0.0;
        if (idx < CLS_N) {
            int cnt = g_cnt[idx];
            if (cnt == 1) {
                int b  = idx / A4;
                int a4 = idx - b * A4;
                int na = a4 / HW;
                int hw = a4 - na * HW;
                int label = (int)g_tsum[idx];
                size_t obase = ((size_t)b * CC * CHN + na * 6 + 5) * HW + hw;
                float m = -1e30f, s = 0.0f, llab = 0.0f;
#pragma unroll
                for (int c = 0; c < CC; c++) {
                    float l = out[obase + (size_t)c * CHN * HW];
                    if (c == label) llab = l;
                    if (l > m) { s = s * __expf(m - l) + 1.0f; m = l; }
                    else       { s += __expf(l - m); }
                }
                float lse = m + __logf(s);
                nll = (double)(lse - llab);
                ns  = 1.0;
            }
        }
#pragma unroll
        for (int o = 16; o > 0; o >>= 1) {
            nll += __shfl_down_sync(0xffffffffu, nll, o);
            ns  += __shfl_down_sync(0xffffffffu, ns,  o);
        }
        __shared__ double s_n[8], s_c[8];
        if ((tid & 31) == 0) { s_n[tid >> 5] = nll; s_c[tid >> 5] = ns; }
        __syncthreads();
        if (tid == 0) {
            double a = 0.0, bsum = 0.0;
#pragma unroll
            for (int w = 0; w < 8; w++) { a += s_n[w]; bsum += s_c[w]; }
            atomicAdd(&g_acc[1], a);
            atomicAdd(&g_acc[2], bsum);
        }
    }
}

// ---------------------------------------------------------------------------
__global__ void k_final(float* __restrict__ res) {
    double N = (double)NBB * (double)A4;
    res[0] = (float)(g_acc[0] / N + g_acc[1] / fmax(g_acc[2], 1.0));
}

// ---------------------------------------------------------------------------
extern "C" void kernel_launch(void* const* d_in, const int* in_sizes, int n_in,
                              void* d_out, int out_size) {
    const float* out_t   = (const float*)d_in[0];
    const float* target  = (const float*)d_in[1];
    const float* anchors = (const float*)d_in[2];
    float* res = (float*)d_out;

    k_zero<<<(CLS_N + 511) / 512, 512>>>();
    k_assign<<<NBB, 64>>>(out_t, target, anchors);
    k_fused<<<MAIN_BLOCKS + CLS_BLOCKS, 256>>>(out_t, anchors);
    k_final<<<1, 1>>>(res);
}

// round 4
// speedup vs baseline: 3.0071x; 1.2066x over previous
#include <cuda_runtime.h>
#include <cstdint>

// Problem constants
#define BB     64
#define CC     20
#define NAA    5
#define HHH    19
#define WWW    19
#define HW     361      // 19*19
#define TT     50
#define NBB    1280     // B*C
#define A4     1805     // NA*H*W
#define CHN    30       // NA*(5+NCPA)
#define EPS12  1e-12f
#define BCEPS  1e-7f
#define MAIN_BLOCKS (NBB * 4)                 // 4 chunks of 512 cells (2/thread)
#define CLS_N   (BB * A4)                     // 115520
#define CLS_BLOCKS ((CLS_N + 255) / 256)      // 452
#define TOTB    (MAIN_BLOCKS + CLS_BLOCKS)

// Static scratch (no allocations allowed; zero at load, self-cleaning after)
__device__ int    g_gt_count[NBB];
__device__ float4 g_gt4[NBB][TT];        // gl, gr, gt, gb (padded w/ dummies)
__device__ float  g_gcn[NBB][TT];        // -0.375*area (-1e30 for pad)
__device__ int    g_asg_n[NBB];
__device__ int    g_asg_cell[NBB][TT];
__device__ float  g_asg_val[NBB][TT][5]; // tx, ty, tw, th, tconf
__device__ int    g_cnt[CLS_N];          // winners per (b, a4) across C
__device__ float  g_tsum[CLS_N];         // sum of winner class ids
__device__ double g_acc[3];              // [0]=dense, [1]=cls nll, [2]=nsel
__device__ unsigned int g_done;

__device__ __forceinline__ float fsigm(float v) {
    return __fdividef(1.0f, 1.0f + __expf(-v));
}

// ---------------------------------------------------------------------------
// One block (64 threads) per nb row.
__global__ void k_assign(const float* __restrict__ out,
                         const float* __restrict__ target,
                         const float* __restrict__ anchors) {
    int nb = blockIdx.x;
    int t  = threadIdx.x;

    __shared__ float s_tg[TT * 5];
    __shared__ int   s_ng, s_nasg;
    __shared__ int   s_cell[TT];

    if (t == 0) { s_ng = TT; s_nasg = 0; }
    const float* tg = target + (size_t)nb * TT * 5;
    for (int i = t; i < TT * 5; i += 64) s_tg[i] = tg[i];
    __syncthreads();

    if (t < TT && s_tg[t * 5 + 1] == 0.0f) atomicMin(&s_ng, t);
    __syncthreads();
    int ng = s_ng;

    float gx = 0.f, gy = 0.f, gw = 0.f, gh = 0.f, ct = 0.f;
    int gi = 0, gj = 0, bn = 0, cell = -1;
    float awb = 1.f, ahb = 1.f;

    if (t < ng) {
        ct = s_tg[t * 5 + 0];
        gx = s_tg[t * 5 + 1] * (float)WWW;
        gy = s_tg[t * 5 + 2] * (float)HHH;
        gw = s_tg[t * 5 + 3] * (float)WWW;
        gh = s_tg[t * 5 + 4] * (float)HHH;

        float best = -1.0f;
#pragma unroll
        for (int a = 0; a < NAA; a++) {
            float aw = __ldg(&anchors[2 * a]);
            float ah = __ldg(&anchors[2 * a + 1]);
            float inter = fminf(gw, aw) * fminf(gh, ah);
            float un = gw * gh + aw * ah - inter;
            float r = __fdividef(inter, fmaxf(un, EPS12));
            if (r > best) { best = r; bn = a; awb = aw; ahb = ah; }
        }
        gi = (int)gx;
        gj = (int)gy;
        cell = bn * HW + gj * WWW + gi;
        s_cell[t] = cell;

        g_gt4[nb][t] = make_float4(gx - 0.5f * gw, gx + 0.5f * gw,
                                   gy - 0.5f * gh, gy + 0.5f * gh);
        g_gcn[nb][t] = -0.375f * gw * gh;
    } else if (t < TT) {
        // dummy pad entry: never triggers the IoU threshold test
        g_gt4[nb][t] = make_float4(0.f, 0.f, 0.f, 0.f);
        g_gcn[nb][t] = -1e30f;
    }
    __syncthreads();

    if (t < ng) {
        // last writer wins for this cell within this nb row
        bool win = true;
        for (int t2 = t + 1; t2 < ng; t2++)
            if (s_cell[t2] == cell) win = false;

        if (win) {
            int b = nb / CC;
            atomicAdd(&g_cnt[b * A4 + cell], 1);
            atomicAdd(&g_tsum[b * A4 + cell], ct);

            const float* ob = out + ((size_t)nb * CHN + bn * 6) * HW + gj * WWW + gi;
            float px = fsigm(ob[0])    + (float)gi;
            float py = fsigm(ob[HW])   + (float)gj;
            float pw = __expf(ob[2 * HW]) * awb;
            float ph = __expf(ob[3 * HW]) * ahb;

            float l  = fmaxf(gx - 0.5f * gw, px - 0.5f * pw);
            float r2 = fminf(gx + 0.5f * gw, px + 0.5f * pw);
            float tp = fmaxf(gy - 0.5f * gh, py - 0.5f * ph);
            float bt = fminf(gy + 0.5f * gh, py + 0.5f * ph);
            float inter = fmaxf(r2 - l, 0.0f) * fmaxf(bt - tp, 0.0f);
            float un = gw * gh + pw * ph - inter;
            float iou = __fdividef(inter, fmaxf(un, EPS12));

            int slot = atomicAdd(&s_nasg, 1);
            g_asg_cell[nb][slot] = cell;
            g_asg_val[nb][slot][0] = gx - (float)gi;
            g_asg_val[nb][slot][1] = gy - (float)gj;
            g_asg_val[nb][slot][2] = __logf(__fdividef(fmaxf(gw, EPS12), awb));
            g_asg_val[nb][slot][3] = __logf(__fdividef(fmaxf(gh, EPS12), ahb));
            g_asg_val[nb][slot][4] = iou;
        }
    }
    __syncthreads();
    if (t == 0) {
        g_gt_count[nb] = ng;
        g_asg_n[nb]    = s_nasg;
    }
}

// ---------------------------------------------------------------------------
// Fused dense losses (2 cells/thread) + class loss + final combine, ONE launch.
__global__ void k_fused(const float* __restrict__ out,
                        const float* __restrict__ anchors,
                        float* __restrict__ res) {
    int tid = threadIdx.x;

    if (blockIdx.x < MAIN_BLOCKS) {
        int nb    = blockIdx.x >> 2;
        int chunk = blockIdx.x & 3;
        int idx0  = chunk * 512 + tid;
        int idx1  = idx0 + 256;

        __shared__ int    s_ng, s_nasg;
        __shared__ float4 s_gt4[TT];
        __shared__ float  s_gcn[TT];
        __shared__ int    s_cell[TT];
        __shared__ float  s_val[TT][5];
        __shared__ uint32_t s_bits[57];

        if (tid == 0) { s_ng = g_gt_count[nb]; s_nasg = g_asg_n[nb]; }
        if (tid < 57) s_bits[tid] = 0u;
        __syncthreads();
        int ng = s_ng, nasg = s_nasg;
        int ngp = ((ng + 4) / 5) * 5;   // padded entries are valid dummies
        for (int i = tid; i < ngp; i += 256) {
            s_gt4[i] = g_gt4[nb][i];
            s_gcn[i] = g_gcn[nb][i];
        }
        for (int i = tid; i < nasg; i += 256) {
            int c = g_asg_cell[nb][i];
            s_cell[i] = c;
            atomicOr(&s_bits[c >> 5], 1u << (c & 31));
        }
        for (int i = tid; i < nasg * 5; i += 256)
            (&s_val[0][0])[i] = (&g_asg_val[nb][0][0])[i];

        // cell setup (global loads issued before the sync to overlap)
        bool lv0 = idx0 < A4, lv1 = idx1 < A4;
        float a0o[5], a1o[5];
        int na0 = 0, hw0 = 0, na1 = 0, hw1 = 0;
        if (lv0) {
            na0 = idx0 / HW; hw0 = idx0 - na0 * HW;
            const float* ob = out + ((size_t)nb * CHN + na0 * 6) * HW + hw0;
#pragma unroll
            for (int j = 0; j < 5; j++) a0o[j] = ob[j * HW];
        }
        if (lv1) {
            na1 = idx1 / HW; hw1 = idx1 - na1 * HW;
            const float* ob = out + ((size_t)nb * CHN + na1 * 6) * HW + hw1;
#pragma unroll
            for (int j = 0; j < 5; j++) a1o[j] = ob[j * HW];
        }
        __syncthreads();

        float pl0 = 1e30f, pr0 = -1e30f, pt0 = 1e30f, pb0 = -1e30f, k10 = 1e30f;
        float pl1 = 1e30f, pr1 = -1e30f, pt1 = 1e30f, pb1 = -1e30f, k11 = 1e30f;
        float x0 = 0.f, y0 = 0.f, c0 = 0.f, x1v = 0.f, y1v = 0.f, c1v = 0.f;
        if (lv0) {
            int hh = hw0 / WWW, ww = hw0 - hh * WWW;
            x0 = fsigm(a0o[0]); y0 = fsigm(a0o[1]); c0 = fsigm(a0o[4]);
            float aw = __ldg(&anchors[2 * na0]), ah = __ldg(&anchors[2 * na0 + 1]);
            float px = x0 + (float)ww, py = y0 + (float)hh;
            float pw = __expf(a0o[2]) * aw, ph = __expf(a0o[3]) * ah;
            pl0 = px - 0.5f * pw; pr0 = px + 0.5f * pw;
            pt0 = py - 0.5f * ph; pb0 = py + 0.5f * ph;
            k10 = 0.375f * pw * ph;
        }
        if (lv1) {
            int hh = hw1 / WWW, ww = hw1 - hh * WWW;
            x1v = fsigm(a1o[0]); y1v = fsigm(a1o[1]); c1v = fsigm(a1o[4]);
            float aw = __ldg(&anchors[2 * na1]), ah = __ldg(&anchors[2 * na1 + 1]);
            float px = x1v + (float)ww, py = y1v + (float)hh;
            float pw = __expf(a1o[2]) * aw, ph = __expf(a1o[3]) * ah;
            pl1 = px - 0.5f * pw; pr1 = px + 0.5f * pw;
            pt1 = py - 0.5f * ph; pb1 = py + 0.5f * ph;
            k11 = 0.375f * pw * ph;
        }

        // IoU>0.6 test, 9 ops/cell/iter:
        //   inter > 0.375*(pa+ga)  <=>  fma(max(iw,0), ih, -0.375*ga) > 0.375*pa
        // single-clamp valid since RHS > 0; max-accumulate, compare once.
        float m0 = -1e30f, m1 = -1e30f;
#pragma unroll 5
        for (int t = 0; t < ngp; t++) {
            float4 g = s_gt4[t];
            float gcn = s_gcn[t];
            float iw0 = fminf(pr0, g.y) - fmaxf(pl0, g.x);
            float ih0 = fminf(pb0, g.w) - fmaxf(pt0, g.z);
            m0 = fmaxf(m0, fmaf(fmaxf(iw0, 0.0f), ih0, gcn));
            float iw1 = fminf(pr1, g.y) - fmaxf(pl1, g.x);
            float ih1 = fminf(pb1, g.w) - fmaxf(pt1, g.z);
            m1 = fmaxf(m1, fmaf(fmaxf(iw1, 0.0f), ih1, gcn));
        }
        bool ov0 = m0 > k10, ov1 = m1 > k11;

        double contrib = 0.0;
#pragma unroll
        for (int cell2 = 0; cell2 < 2; cell2++) {
            bool live = cell2 ? lv1 : lv0;
            if (!live) continue;
            int idx = cell2 ? idx1 : idx0;
            float x = cell2 ? x1v : x0, y = cell2 ? y1v : y0, conf = cell2 ? c1v : c0;
            float o2 = cell2 ? a1o[2] : a0o[2], o3 = cell2 ? a1o[3] : a0o[3];
            bool over = cell2 ? ov1 : ov0;

            float cfm = over ? 0.0f : 1.0f;
            float tx = 0.5f, ty = 0.5f, tw = 0.0f, th = 0.0f, tconf = 0.0f;
            if (s_bits[idx >> 5] & (1u << (idx & 31))) {
                for (int k = 0; k < nasg; k++) {
                    if (s_cell[k] == idx) {
                        cfm = 1.0f;
                        tx = s_val[k][0]; ty = s_val[k][1];
                        tw = s_val[k][2]; th = s_val[k][3];
                        tconf = s_val[k][4];
                    }
                }
            }
            float pxc = fminf(fmaxf(x, BCEPS), 1.0f - BCEPS);
            float pyc = fminf(fmaxf(y, BCEPS), 1.0f - BCEPS);
            float bx = -(tx * __logf(pxc) + (1.0f - tx) * __logf(1.0f - pxc));
            float by = -(ty * __logf(pyc) + (1.0f - ty) * __logf(1.0f - pyc));
            float dw = o2 - tw, dh = o3 - th;
            float dc = cfm * (conf - tconf);
            contrib += (double)(bx + by + 0.5f * (dw * dw + dh * dh) + 0.5f * dc * dc);
        }

#pragma unroll
        for (int o = 16; o > 0; o >>= 1)
            contrib += __shfl_down_sync(0xffffffffu, contrib, o);
        __shared__ double s_red[8];
        if ((tid & 31) == 0) s_red[tid >> 5] = contrib;
        __syncthreads();
        if (tid == 0) {
            double s = 0.0;
#pragma unroll
            for (int w = 0; w < 8; w++) s += s_red[w];
            atomicAdd(&g_acc[0], s);
        }
    } else {
        // ---- class-loss blocks (self-cleaning: reset g_cnt/g_tsum) ----
        int idx = (blockIdx.x - MAIN_BLOCKS) * 256 + tid;
        double nll = 0.0, ns = 0.0;
        if (idx < CLS_N) {
            int cnt = g_cnt[idx];
            if (cnt != 0) {
                float tsum = g_tsum[idx];
                g_cnt[idx] = 0;
                g_tsum[idx] = 0.0f;
                if (cnt == 1) {
                    int b  = idx / A4;
                    int a4 = idx - b * A4;
                    int na = a4 / HW;
                    int hw = a4 - na * HW;
                    int label = (int)tsum;
                    size_t obase = ((size_t)b * CC * CHN + na * 6 + 5) * HW + hw;
                    float m = -1e30f, s = 0.0f, llab = 0.0f;
#pragma unroll
                    for (int c = 0; c < CC; c++) {
                        float l = out[obase + (size_t)c * CHN * HW];
                        if (c == label) llab = l;
                        if (l > m) { s = s * __expf(m - l) + 1.0f; m = l; }
                        else       { s += __expf(l - m); }
                    }
                    float lse = m + __logf(s);
                    nll = (double)(lse - llab);
                    ns  = 1.0;
                }
            }
        }
#pragma unroll
        for (int o = 16; o > 0; o >>= 1) {
            nll += __shfl_down_sync(0xffffffffu, nll, o);
            ns  += __shfl_down_sync(0xffffffffu, ns,  o);
        }
        __shared__ double s_n[8], s_c[8];
        if ((tid & 31) == 0) { s_n[tid >> 5] = nll; s_c[tid >> 5] = ns; }
        __syncthreads();
        if (tid == 0) {
            double a = 0.0, bsum = 0.0;
#pragma unroll
            for (int w = 0; w < 8; w++) { a += s_n[w]; bsum += s_c[w]; }
            if (a != 0.0)    atomicAdd(&g_acc[1], a);
            if (bsum != 0.0) atomicAdd(&g_acc[2], bsum);
        }
    }

    // ---- last-block final combine (also resets g_acc for next replay) ----
    if (tid == 0) {
        __threadfence();
        unsigned int old = atomicAdd(&g_done, 1u);
        if (old == TOTB - 1) {
            double a0 = __longlong_as_double(
                atomicExch((unsigned long long*)&g_acc[0], 0ULL));
            double a1 = __longlong_as_double(
                atomicExch((unsigned long long*)&g_acc[1], 0ULL));
            double a2 = __longlong_as_double(
                atomicExch((unsigned long long*)&g_acc[2], 0ULL));
            double N = (double)NBB * (double)A4;
            res[0] = (float)(a0 / N + a1 / fmax(a2, 1.0));
            g_done = 0;
        }
    }
}

// ---------------------------------------------------------------------------
extern "C" void kernel_launch(void* const* d_in, const int* in_sizes, int n_in,
                              void* d_out, int out_size) {
    const float* out_t   = (const float*)d_in[0];
    const float* target  = (const float*)d_in[1];
    const float* anchors = (const float*)d_in[2];
    float* res = (float*)d_out;

    k_assign<<<NBB, 64>>>(out_t, target, anchors);
    k_fused<<<TOTB, 256>>>(out_t, anchors, res);
}

// round 6
// speedup vs baseline: 3.6914x; 1.2276x over previous
#include <cuda_runtime.h>
#include <cstdint>

// Problem constants
#define BB     64
#define CC     20
#define NAA    5
#define HHH    19
#define WWW    19
#define HW     361      // 19*19
#define TT     50
#define NBB    1280     // B*C
#define A4     1805     // NA*H*W
#define CHN    30       // NA*(5+NCPA)
#define EPS12  1e-12f
#define BCEPS  1e-7f
#define RB     4                              // rows per band
#define BANDS  5                              // ceil(19/4)
#define TILE   (NAA * RB * WWW)               // 380 cells per band-block
#define MAIN_BLOCKS (NBB * BANDS)             // 6400
#define CLS_N   (BB * A4)                     // 115520
#define CLS_BLOCKS ((CLS_N + 127) / 128)      // 903
#define TOTB    (MAIN_BLOCKS + CLS_BLOCKS)
#define BIGS    1e18f

// Static scratch (no allocations; zero at load, self-cleaning across replays)
__device__ int    g_gt_count[NBB];
__device__ float4 g_gt4[NBB][TT];        // gl, gr, gtop, gbot
__device__ float  g_gcn[NBB][TT];        // -0.375*gt_area
__device__ int    g_asg_n[NBB];
__device__ int    g_asg_cell[NBB][TT];
__device__ float  g_asg_val[NBB][TT][5]; // tx, ty, tw, th, tconf
__device__ int    g_cnt[CLS_N];          // winners per (b, a4) across C
__device__ float  g_tsum[CLS_N];         // sum of winner class ids
__device__ double g_acc[3];              // [0]=dense, [1]=cls nll, [2]=nsel
__device__ unsigned int g_done;

__device__ __forceinline__ float fsigm(float v) {
    return __fdividef(1.0f, 1.0f + __expf(-v));
}

// ---------------------------------------------------------------------------
// One block (64 threads) per nb row.
__global__ void k_assign(const float* __restrict__ out,
                         const float* __restrict__ target,
                         const float* __restrict__ anchors) {
    int nb = blockIdx.x;
    int t  = threadIdx.x;

    __shared__ float s_tg[TT * 5];
    __shared__ int   s_ng, s_nasg;
    __shared__ int   s_cell[TT];

    if (t == 0) { s_ng = TT; s_nasg = 0; }
    const float* tg = target + (size_t)nb * TT * 5;
    for (int i = t; i < TT * 5; i += 64) s_tg[i] = tg[i];
    __syncthreads();

    if (t < TT && s_tg[t * 5 + 1] == 0.0f) atomicMin(&s_ng, t);
    __syncthreads();
    int ng = s_ng;

    float gx = 0.f, gy = 0.f, gw = 0.f, gh = 0.f, ct = 0.f;
    int gi = 0, gj = 0, bn = 0, cell = -1;
    float awb = 1.f, ahb = 1.f;

    if (t < ng) {
        ct = s_tg[t * 5 + 0];
        gx = s_tg[t * 5 + 1] * (float)WWW;
        gy = s_tg[t * 5 + 2] * (float)HHH;
        gw = s_tg[t * 5 + 3] * (float)WWW;
        gh = s_tg[t * 5 + 4] * (float)HHH;

        float best = -1.0f;
#pragma unroll
        for (int a = 0; a < NAA; a++) {
            float aw = __ldg(&anchors[2 * a]);
            float ah = __ldg(&anchors[2 * a + 1]);
            float inter = fminf(gw, aw) * fminf(gh, ah);
            float un = gw * gh + aw * ah - inter;
            float r = __fdividef(inter, fmaxf(un, EPS12));
            if (r > best) { best = r; bn = a; awb = aw; ahb = ah; }
        }
        gi = (int)gx;
        gj = (int)gy;
        cell = bn * HW + gj * WWW + gi;   // anchor-major cell id
        s_cell[t] = cell;

        g_gt4[nb][t] = make_float4(gx - 0.5f * gw, gx + 0.5f * gw,
                                   gy - 0.5f * gh, gy + 0.5f * gh);
        g_gcn[nb][t] = -0.375f * gw * gh;
    }
    __syncthreads();

    if (t < ng) {
        // last writer wins for this cell within this nb row
        bool win = true;
        for (int t2 = t + 1; t2 < ng; t2++)
            if (s_cell[t2] == cell) win = false;

        if (win) {
            int b = nb / CC;
            atomicAdd(&g_cnt[b * A4 + cell], 1);
            atomicAdd(&g_tsum[b * A4 + cell], ct);

            const float* ob = out + ((size_t)nb * CHN + bn * 6) * HW + gj * WWW + gi;
            float px = fsigm(ob[0])    + (float)gi;
            float py = fsigm(ob[HW])   + (float)gj;
            float pw = __expf(ob[2 * HW]) * awb;
            float ph = __expf(ob[3 * HW]) * ahb;

            float l  = fmaxf(gx - 0.5f * gw, px - 0.5f * pw);
            float r2 = fminf(gx + 0.5f * gw, px + 0.5f * pw);
            float tp = fmaxf(gy - 0.5f * gh, py - 0.5f * ph);
            float bt = fminf(gy + 0.5f * gh, py + 0.5f * ph);
            float inter = fmaxf(r2 - l, 0.0f) * fmaxf(bt - tp, 0.0f);
            float un = gw * gh + pw * ph - inter;
            float iou = __fdividef(inter, fmaxf(un, EPS12));

            int slot = atomicAdd(&s_nasg, 1);
            g_asg_cell[nb][slot] = cell;
            g_asg_val[nb][slot][0] = gx - (float)gi;
            g_asg_val[nb][slot][1] = gy - (float)gj;
            g_asg_val[nb][slot][2] = __logf(__fdividef(fmaxf(gw, EPS12), awb));
            g_asg_val[nb][slot][3] = __logf(__fdividef(fmaxf(gh, EPS12), ahb));
            g_asg_val[nb][slot][4] = iou;
        }
    }
    __syncthreads();
    if (t == 0) {
        g_gt_count[nb] = ng;
        g_asg_n[nb]    = s_nasg;
    }
}

// ---------------------------------------------------------------------------
// Fused dense losses (band-tiled, y-filtered gts, 3 cells/thread) + class
// loss + final combine, in ONE launch.
__global__ void __launch_bounds__(128, 8)
k_fused(const float* __restrict__ out,
        const float* __restrict__ anchors,
        float* __restrict__ res) {
    int tid = threadIdx.x;

    if (blockIdx.x < MAIN_BLOCKS) {
        int nb   = blockIdx.x / BANDS;
        int band = blockIdx.x - nb * BANDS;
        int h0   = band * RB;

        // ---- decode 3 cells & issue global loads early ----
        bool  lv[3];
        int   gidx[3], na_[3], ww_[3], hh_[3];
        float o_[3][5];
#pragma unroll
        for (int i = 0; i < 3; i++) {
            int c = tid + i * 128;
            int na = c / (RB * WWW);
            int rem = c - na * (RB * WWW);
            int r = rem / WWW;
            int ww = rem - r * WWW;
            int hh = h0 + r;
            bool live = (c < TILE) && (hh < HHH);
            lv[i] = live; na_[i] = na; ww_[i] = ww; hh_[i] = hh;
            if (live) {
                int hw = hh * WWW + ww;
                gidx[i] = na * HW + hw;
                const float* ob = out + ((size_t)nb * CHN + na * 6) * HW + hw;
#pragma unroll
                for (int j = 0; j < 5; j++) o_[i][j] = ob[j * HW];
            } else {
                gidx[i] = -1;
#pragma unroll
                for (int j = 0; j < 5; j++) o_[i][j] = 0.0f;
            }
        }

        // ---- shared: y-filtered gt list + assignment tables ----
        __shared__ int    s_m, s_nasg;
        __shared__ float4 s_g[TT + 5];
        __shared__ float  s_gcn[TT + 5];
        __shared__ int    s_cell[TT];
        __shared__ float  s_val[TT][5];
        __shared__ uint32_t s_bits[57];

        if (tid == 0) { s_m = 0; s_nasg = g_asg_n[nb]; }
        if (tid < 57) s_bits[tid] = 0u;
        __syncthreads();

        if (tid < TT && tid < g_gt_count[nb]) {
            float4 g = g_gt4[nb][tid];
            // row window: gt matters only for hh in (gy-0.4gh-1, gy+0.4gh)
            float ylo = 0.9f * g.z + 0.1f * g.w;   // gy - 0.4*gh
            float yhi = 0.1f * g.z + 0.9f * g.w;   // gy + 0.4*gh
            if ((float)h0 < yhi + 0.01f && (float)(h0 + RB) > ylo - 0.01f) {
                int pos = atomicAdd(&s_m, 1);
                s_g[pos]   = g;
                s_gcn[pos] = g_gcn[nb][tid];
            }
        }
        __syncthreads();
        int m_raw = s_m;
        int mp = ((m_raw + 4) / 5) * 5;
        if (tid >= m_raw && tid < mp) {      // pad with inert dummies
            s_g[tid]   = make_float4(0.f, 0.f, 0.f, 0.f);
            s_gcn[tid] = -1e30f;
        }
        int nasg = s_nasg;
        for (int i = tid; i < nasg; i += 128) {
            int c = g_asg_cell[nb][i];
            s_cell[i] = c;
            atomicOr(&s_bits[c >> 5], 1u << (c & 31));
        }
        for (int i = tid; i < nasg * 5; i += 128)
            (&s_val[0][0])[i] = (&g_asg_val[nb][0][0])[i];
        __syncthreads();

        // ---- per-cell pred box setup ----
        float pl[3], pr[3], pt[3], pb[3], k1[3], mm[3];
#pragma unroll
        for (int i = 0; i < 3; i++) {
            if (lv[i]) {
                float x = fsigm(o_[i][0]);
                float y = fsigm(o_[i][1]);
                float aw = __ldg(&anchors[2 * na_[i]]);
                float ah = __ldg(&anchors[2 * na_[i] + 1]);
                float px = x + (float)ww_[i];
                float py = y + (float)hh_[i];
                float pw = __expf(o_[i][2]) * aw;
                float ph = __expf(o_[i][3]) * ah;
                pl[i] = px - 0.5f * pw; pr[i] = px + 0.5f * pw;
                pt[i] = py - 0.5f * ph; pb[i] = py + 0.5f * ph;
                k1[i] = 0.375f * pw * ph;
            } else {
                pl[i] = BIGS; pr[i] = -BIGS;
                pt[i] = BIGS; pb[i] = -BIGS;
                k1[i] = 1e30f;
            }
            mm[i] = -1e30f;
        }

        // ---- filtered IoU>0.6 loop (9 ops/cell/iter) ----
#pragma unroll 5
        for (int t = 0; t < mp; t++) {
            float4 g = s_g[t];
            float gcn = s_gcn[t];
#pragma unroll
            for (int i = 0; i < 3; i++) {
                float iw = fminf(pr[i], g.y) - fmaxf(pl[i], g.x);
                float ih = fminf(pb[i], g.w) - fmaxf(pt[i], g.z);
                mm[i] = fmaxf(mm[i], fmaf(fmaxf(iw, 0.0f), ih, gcn));
            }
        }

        // ---- epilogue: BCE + MSE per cell ----
        double contrib = 0.0;
#pragma unroll
        for (int i = 0; i < 3; i++) {
            if (!lv[i]) continue;
            int idx = gidx[i];
            float x = fsigm(o_[i][0]);
            float y = fsigm(o_[i][1]);
            float conf = fsigm(o_[i][4]);
            float o2 = o_[i][2], o3 = o_[i][3];

            float cfm = (mm[i] > k1[i]) ? 0.0f : 1.0f;
            float tx = 0.5f, ty = 0.5f, tw = 0.0f, th = 0.0f, tconf = 0.0f;
            if (s_bits[idx >> 5] & (1u << (idx & 31))) {
                for (int k = 0; k < nasg; k++) {
                    if (s_cell[k] == idx) {
                        cfm = 1.0f;
                        tx = s_val[k][0]; ty = s_val[k][1];
                        tw = s_val[k][2]; th = s_val[k][3];
                        tconf = s_val[k][4];
                    }
                }
            }
            float pxc = fminf(fmaxf(x, BCEPS), 1.0f - BCEPS);
            float pyc = fminf(fmaxf(y, BCEPS), 1.0f - BCEPS);
            float bx = -(tx * __logf(pxc) + (1.0f - tx) * __logf(1.0f - pxc));
            float by = -(ty * __logf(pyc) + (1.0f - ty) * __logf(1.0f - pyc));
            float dw = o2 - tw, dh = o3 - th;
            float dc = cfm * (conf - tconf);
            contrib += (double)(bx + by + 0.5f * (dw * dw + dh * dh) + 0.5f * dc * dc);
        }

#pragma unroll
        for (int o = 16; o > 0; o >>= 1)
            contrib += __shfl_down_sync(0xffffffffu, contrib, o);
        __shared__ double s_red[4];
        if ((tid & 31) == 0) s_red[tid >> 5] = contrib;
        __syncthreads();
        if (tid == 0) {
            double s = s_red[0] + s_red[1] + s_red[2] + s_red[3];
            atomicAdd(&g_acc[0], s);
        }
    } else {
        // ---- class-loss blocks (self-cleaning: reset g_cnt/g_tsum) ----
        int idx = (blockIdx.x - MAIN_BLOCKS) * 128 + tid;
        double nll = 0.0, ns = 0.0;
        if (idx < CLS_N) {
            int cnt = g_cnt[idx];
            if (cnt != 0) {
                float tsum = g_tsum[idx];
                g_cnt[idx] = 0;
                g_tsum[idx] = 0.0f;
                if (cnt == 1) {
                    int b  = idx / A4;
                    int a4 = idx - b * A4;
                    int na = a4 / HW;
                    int hw = a4 - na * HW;
                    int label = (int)tsum;
                    size_t obase = ((size_t)b * CC * CHN + na * 6 + 5) * HW + hw;
                    float m = -1e30f, s = 0.0f, llab = 0.0f;
#pragma unroll
                    for (int c = 0; c < CC; c++) {
                        float l = out[obase + (size_t)c * CHN * HW];
                        if (c == label) llab = l;
                        if (l > m) { s = s * __expf(m - l) + 1.0f; m = l; }
                        else       { s += __expf(l - m); }
                    }
                    float lse = m + __logf(s);
                    nll = (double)(lse - llab);
                    ns  = 1.0;
                }
            }
        }
#pragma unroll
        for (int o = 16; o > 0; o >>= 1) {
            nll += __shfl_down_sync(0xffffffffu, nll, o);
            ns  += __shfl_down_sync(0xffffffffu, ns,  o);
        }
        __shared__ double s_n[4], s_c[4];
        if ((tid & 31) == 0) { s_n[tid >> 5] = nll; s_c[tid >> 5] = ns; }
        __syncthreads();
        if (tid == 0) {
            double a = s_n[0] + s_n[1] + s_n[2] + s_n[3];
            double bsum = s_c[0] + s_c[1] + s_c[2] + s_c[3];
            if (a != 0.0)    atomicAdd(&g_acc[1], a);
            if (bsum != 0.0) atomicAdd(&g_acc[2], bsum);
        }
    }

    // ---- last-block final combine (also resets g_acc for next replay) ----
    if (tid == 0) {
        __threadfence();
        unsigned int old = atomicAdd(&g_done, 1u);
        if (old == TOTB - 1) {
            double a0 = __longlong_as_double(
                atomicExch((unsigned long long*)&g_acc[0], 0ULL));
            double a1 = __longlong_as_double(
                atomicExch((unsigned long long*)&g_acc[1], 0ULL));
            double a2 = __longlong_as_double(
                atomicExch((unsigned long long*)&g_acc[2], 0ULL));
            double N = (double)NBB * (double)A4;
            res[0] = (float)(a0 / N + a1 / fmax(a2, 1.0));
            g_done = 0;
        }
    }
}

// ---------------------------------------------------------------------------
extern "C" void kernel_launch(void* const* d_in, const int* in_sizes, int n_in,
                              void* d_out, int out_size) {
    const float* out_t   = (const float*)d_in[0];
    const float* target  = (const float*)d_in[1];
    const float* anchors = (const float*)d_in[2];
    float* res = (float*)d_out;

    k_assign<<<NBB, 64>>>(out_t, target, anchors);
    k_fused<<<TOTB, 128>>>(out_t, anchors, res);
}